// round 10
// baseline (speedup 1.0000x reference)
#include <cuda_runtime.h>
#include <cstdint>
#include <math.h>

// Problem constants
#define BB 16
#define SS 256
#define VV 32000
#define HH 1024
#define MM (SS*BB)        // 4096 rows, time-major m = s*16+b
#define G4 (4*HH)         // 4096 packed gate columns

// ---------------- static device scratch ----------------
__device__ float g_WhP[G4*HH];            // recurrent weights fp32 [p][k]
__device__ float g_WxP[G4*HH];            // input weights, tf32-rounded [p][k]
__device__ float g_bpack[G4];
__device__ float g_xe  [(size_t)MM*HH];   // gathered embeddings, tf32-rounded
__device__ float g_embR[(size_t)VV*HH];   // emb tf32-rounded (projection B)
__device__ float g_xpart[(size_t)MM*G4];  // x@Wx.T + b
__device__ float g_ysT [(size_t)MM*HH];   // h history, tf32-rounded (projection A)
__device__ float g_h[BB*HH];
__device__ unsigned long long g_bar = 0ULL;

// ---------------- helpers ----------------
__device__ __forceinline__ uint32_t smem_u32(const void* p) {
    uint32_t a;
    asm("{ .reg .u64 t; cvta.to.shared.u64 t, %1; cvt.u32.u64 %0, t; }" : "=r"(a) : "l"(p));
    return a;
}
__device__ __forceinline__ float rna_tf32(float x) {
    uint32_t r;
    asm("cvt.rna.tf32.f32 %0, %1;" : "=r"(r) : "f"(x));
    return __uint_as_float(r);
}
__device__ __forceinline__ void cp_async16(uint32_t saddr, const void* gaddr) {
    asm volatile("cp.async.cg.shared.global [%0], [%1], 16;" :: "r"(saddr), "l"(gaddr));
}
__device__ __forceinline__ void cp_commit() {
    asm volatile("cp.async.commit_group;");
}
__device__ __forceinline__ void cp_wait1() {
    asm volatile("cp.async.wait_group 1;");
}
__device__ __forceinline__ void ldm_x4(uint32_t* r, uint32_t addr) {
    asm volatile("ldmatrix.sync.aligned.m8n8.x4.shared.b16 {%0,%1,%2,%3}, [%4];"
                 : "=r"(r[0]), "=r"(r[1]), "=r"(r[2]), "=r"(r[3]) : "r"(addr));
}
__device__ __forceinline__ void mma_tf32(float* c, const uint32_t* a, uint32_t b0, uint32_t b1) {
    asm volatile(
        "mma.sync.aligned.m16n8k8.row.col.f32.tf32.tf32.f32 "
        "{%0,%1,%2,%3}, {%4,%5,%6,%7}, {%8,%9}, {%0,%1,%2,%3};"
        : "+f"(c[0]), "+f"(c[1]), "+f"(c[2]), "+f"(c[3])
        : "r"(a[0]), "r"(a[1]), "r"(a[2]), "r"(a[3]), "r"(b0), "r"(b1));
}

// ---------------- prep kernels ----------------
__global__ void pack_kernel(const float* __restrict__ Wi, const float* __restrict__ Wf,
                            const float* __restrict__ Wo, const float* __restrict__ Wc,
                            const float* __restrict__ bi, const float* __restrict__ bf,
                            const float* __restrict__ bo, const float* __restrict__ bc)
{
    int idx4 = blockIdx.x*256 + threadIdx.x;     // over G4*256
    int p = idx4 >> 8, kq = idx4 & 255;
    int n = p >> 2, gt = p & 3;
    const float* W = (gt==0)?Wi:(gt==1)?Wf:(gt==2)?Wo:Wc;
    float4 vh = *(const float4*)(W + (size_t)n*2048 + kq*4);
    float4 vx = *(const float4*)(W + (size_t)n*2048 + 1024 + kq*4);
    *(float4*)(g_WhP + (size_t)p*HH + kq*4) = vh;
    vx.x = rna_tf32(vx.x); vx.y = rna_tf32(vx.y); vx.z = rna_tf32(vx.z); vx.w = rna_tf32(vx.w);
    *(float4*)(g_WxP + (size_t)p*HH + kq*4) = vx;
    if (kq == 0) {
        const float* bp = (gt==0)?bi:(gt==1)?bf:(gt==2)?bo:bc;
        g_bpack[p] = bp[n];
    }
}

__global__ void round_emb_kernel(const float* __restrict__ emb)
{
    size_t i = ((size_t)blockIdx.x*256 + threadIdx.x) * 4;   // VV*HH/4 threads
    float4 v = *(const float4*)(emb + i);
    v.x = rna_tf32(v.x); v.y = rna_tf32(v.y); v.z = rna_tf32(v.z); v.w = rna_tf32(v.w);
    *(float4*)(g_embR + i) = v;
}

__global__ void gather_xe_kernel(const int* __restrict__ x, const float* __restrict__ emb)
{
    int idx4 = blockIdx.x*256 + threadIdx.x;     // over MM*256
    int m = idx4 >> 8, q = idx4 & 255;
    int tok = x[(m & 15)*SS + (m >> 4)];
    float4 v = *(const float4*)(emb + (size_t)tok*HH + q*4);
    v.x = rna_tf32(v.x); v.y = rna_tf32(v.y); v.z = rna_tf32(v.z); v.w = rna_tf32(v.w);
    *(float4*)(g_xe + (size_t)m*HH + q*4) = v;
}

// ---------------- tf32 mma.sync NT GEMM: C[m][n] = A[m][:] . B[n][:] + bias[n] ----------------
// A: [rowsA][HH] row-major, B: [rowsB][HH] row-major (both tf32-rounded)
// MODE 0: C = g_xpart (row m direct, stride NN)
// MODE 1: C = logits, row remap m -> (m&15)*SS + (m>>4), stride NN
// CTA tile 128x128, 8 warps (2m x 4n), warp tile 64x32, mma m16n8k8, BK=32, 3-stage cp.async.
#define KTILE 32
#define KI (HH/KTILE)              // 32
#define ASTR 36                    // smem row stride in floats (pad 4)
#define STG_FLOATS (128*ASTR*2)    // A + B per stage = 9216 floats
#define SMEM_GEMM (3*STG_FLOATS*4) // 110592 bytes

template<int MODE, int NN>
__global__ void __launch_bounds__(256, 1)
gemm_mma(const float* __restrict__ A, const float* __restrict__ B,
         const float* __restrict__ bias, float* __restrict__ C)
{
    extern __shared__ __align__(128) float sm[];
    const int tid = threadIdx.x;
    const int wid = tid >> 5, lane = tid & 31;
    const int warp_m = wid >> 2;           // 0..1
    const int warp_n = wid & 3;            // 0..3
    const int m_base = blockIdx.x * 128;
    const int n_base = blockIdx.y * 128;

    // ---- loader precompute: 4 chunks of 16B for A and for B per thread ----
    int lrowA[4], lccA[4];
    #pragma unroll
    for (int i = 0; i < 4; i++) {
        int chunk = tid + i*256;           // 0..1023
        lrowA[i] = chunk >> 3;
        lccA[i]  = chunk & 7;
    }
    const uint32_t smb = smem_u32(sm);

    // ---- ldmatrix per-lane address pieces (A fragments) ----
    const int matid = lane >> 3;
    const int fr_row = (lane & 7) + (matid & 1)*8;
    const int fr_colb = (matid >> 1) * 16;          // byte offset within 32B k-step
    // byte addr of A fragment base (stage 0, mt=0, ko=0):
    const uint32_t a_frag_base = smb + (uint32_t)(warp_m*64 + fr_row) * (ASTR*4) + fr_colb;

    // ---- B fragment smem float-index base ----
    const int b_frag_base = 128*ASTR + (warp_n*32 + (lane >> 2))*ASTR + (lane & 3);

    float acc[4][4][4];
    #pragma unroll
    for (int mt = 0; mt < 4; mt++)
        #pragma unroll
        for (int nt = 0; nt < 4; nt++)
            #pragma unroll
            for (int r = 0; r < 4; r++) acc[mt][nt][r] = 0.f;

    // ---- async load of one k-tile into stage st ----
    auto issue = [&](int st, int kt) {
        float* As = sm + st*STG_FLOATS;
        float* Bs = As + 128*ASTR;
        #pragma unroll
        for (int i = 0; i < 4; i++) {
            const float* ga = A + (size_t)(m_base + lrowA[i])*HH + kt*KTILE + lccA[i]*4;
            const float* gb = B + (size_t)(n_base + lrowA[i])*HH + kt*KTILE + lccA[i]*4;
            cp_async16(smem_u32(&As[lrowA[i]*ASTR + lccA[i]*4]), ga);
            cp_async16(smem_u32(&Bs[lrowA[i]*ASTR + lccA[i]*4]), gb);
        }
        cp_commit();
    };

    issue(0, 0);
    issue(1, 1);

    for (int kt = 0; kt < KI; kt++) {
        cp_wait1();
        __syncthreads();
        if (kt + 2 < KI) issue((kt+2) % 3, kt+2);

        const int st = kt % 3;
        const uint32_t a_st = a_frag_base + (uint32_t)st * (STG_FLOATS*4);
        const float* Bs = sm + st*STG_FLOATS;

        #pragma unroll
        for (int ko = 0; ko < 4; ko++) {
            uint32_t afr[4][4];
            #pragma unroll
            for (int mt = 0; mt < 4; mt++)
                ldm_x4(afr[mt], a_st + mt*(16*ASTR*4) + ko*32);
            uint32_t b0[4], b1[4];
            #pragma unroll
            for (int nt = 0; nt < 4; nt++) {
                int bi_ = b_frag_base + nt*(8*ASTR) + ko*8;
                b0[nt] = __float_as_uint(Bs[bi_]);
                b1[nt] = __float_as_uint(Bs[bi_ + 4]);
            }
            #pragma unroll
            for (int mt = 0; mt < 4; mt++)
                #pragma unroll
                for (int nt = 0; nt < 4; nt++)
                    mma_tf32(acc[mt][nt], afr[mt], b0[nt], b1[nt]);
        }
    }

    // ---- epilogue: bias add + store ----
    #pragma unroll
    for (int mt = 0; mt < 4; mt++) {
        int r0 = m_base + warp_m*64 + mt*16 + (lane >> 2);
        int r1 = r0 + 8;
        size_t off0, off1;
        if (MODE == 0) {
            off0 = (size_t)r0 * NN;
            off1 = (size_t)r1 * NN;
        } else {
            off0 = (size_t)((r0 & 15)*SS + (r0 >> 4)) * (size_t)NN;
            off1 = (size_t)((r1 & 15)*SS + (r1 >> 4)) * (size_t)NN;
        }
        #pragma unroll
        for (int nt = 0; nt < 4; nt++) {
            int col = n_base + warp_n*32 + nt*8 + 2*(lane & 3);
            float2 bv = *(const float2*)(bias + col);
            float2 o0, o1;
            o0.x = acc[mt][nt][0] + bv.x; o0.y = acc[mt][nt][1] + bv.y;
            o1.x = acc[mt][nt][2] + bv.x; o1.y = acc[mt][nt][3] + bv.y;
            *(float2*)(C + off0 + col) = o0;
            *(float2*)(C + off1 + col) = o1;
        }
    }
}

// ---------------- persistent recurrent kernel ----------------
#define GRID_R 128
#define THR_R  256
#define WSH_STRIDE 36
#define HS_STRIDE  20
#define RED_STRIDE 36
#define SMEM_SCAN ((HH*WSH_STRIDE + HH*HS_STRIDE)*4)

__device__ __forceinline__ void grid_barrier() {
    __syncthreads();
    if (threadIdx.x == 0) {
        __threadfence();
        unsigned long long ticket = atomicAdd(&g_bar, 1ULL);
        unsigned long long target = (ticket / GRID_R + 1ULL) * (unsigned long long)GRID_R;
        while (*((volatile unsigned long long*)&g_bar) < target) { }
        __threadfence();
    }
    __syncthreads();
}

__global__ void __launch_bounds__(THR_R, 1) lstm_rec(float* __restrict__ out_hc)
{
    extern __shared__ float smr[];
    float* Wsh = smr;                        // [k][c], stride 36
    float* hs  = smr + HH*WSH_STRIDE;        // [k][b], stride 20 (reused as red buffer)

    const int tid = threadIdx.x;
    const int cta = blockIdx.x;
    const int tk = tid & 31;
    const int tb = (tid >> 5) & 1;
    const int tc = tid >> 6;
    const int b0 = tb*8, c0 = tc*8;

    {
        int c = tid >> 3, kq = tid & 7;
        const float* src = g_WhP + (size_t)(cta*32 + c)*HH;
        #pragma unroll 4
        for (int it = 0; it < 32; it++) {
            int k0 = kq*4 + it*32;
            float4 v = *(const float4*)(src + k0);
            Wsh[(k0+0)*WSH_STRIDE + c] = v.x;
            Wsh[(k0+1)*WSH_STRIDE + c] = v.y;
            Wsh[(k0+2)*WSH_STRIDE + c] = v.z;
            Wsh[(k0+3)*WSH_STRIDE + c] = v.w;
        }
    }
    if (tid < 128) g_h[cta*128 + tid] = 0.f;

    float c_state = 0.f;

    grid_barrier();

    for (int s = 0; s < SS; s++) {
        {
            int b = tid >> 4, nq = tid & 15;
            const float* hp = g_h + b*HH;
            #pragma unroll 4
            for (int it = 0; it < 16; it++) {
                int n0 = nq*4 + it*64;
                float4 v = __ldcg((const float4*)(hp + n0));
                hs[(n0+0)*HS_STRIDE + b] = v.x;
                hs[(n0+1)*HS_STRIDE + b] = v.y;
                hs[(n0+2)*HS_STRIDE + b] = v.z;
                hs[(n0+3)*HS_STRIDE + b] = v.w;
            }
        }
        __syncthreads();

        float acc[8][8];
        #pragma unroll
        for (int i = 0; i < 8; i++)
            #pragma unroll
            for (int j = 0; j < 8; j++) acc[i][j] = 0.f;

        #pragma unroll 4
        for (int kk = 0; kk < 32; kk++) {
            int k = kk*32 + tk;
            float a[8], w[8];
            *(float4*)&a[0] = *(const float4*)&hs[k*HS_STRIDE + b0];
            *(float4*)&a[4] = *(const float4*)&hs[k*HS_STRIDE + b0 + 4];
            *(float4*)&w[0] = *(const float4*)&Wsh[k*WSH_STRIDE + c0];
            *(float4*)&w[4] = *(const float4*)&Wsh[k*WSH_STRIDE + c0 + 4];
            #pragma unroll
            for (int i = 0; i < 8; i++)
                #pragma unroll
                for (int j = 0; j < 8; j++)
                    acc[i][j] += a[i]*w[j];
        }
        __syncthreads();

        float* red = hs;
        #pragma unroll
        for (int i = 0; i < 8; i++)
            #pragma unroll
            for (int j = 0; j < 8; j++)
                red[((c0+j)*16 + (b0+i))*RED_STRIDE + tk] = acc[i][j];
        __syncthreads();

        if (tid < 128) {
            int b = tid & 15, nl = tid >> 4;
            float g[4];
            #pragma unroll
            for (int gt = 0; gt < 4; gt++) {
                int cl = nl*4 + gt;
                const float* rp = red + (cl*16 + b)*RED_STRIDE;
                float ssum = 0.f;
                #pragma unroll
                for (int t = 0; t < 32; t += 4) {
                    float4 v = *(const float4*)(rp + t);
                    ssum += (v.x + v.y) + (v.z + v.w);
                }
                g[gt] = ssum + __ldcg(&g_xpart[((size_t)s*BB + b)*G4 + cta*32 + cl]);
            }
            float i_g = 1.f/(1.f + expf(-g[0]));
            float f_g = 1.f/(1.f + expf(-g[1]));
            float o_g = 1.f/(1.f + expf(-g[2]));
            float cc  = tanhf(g[3]);
            c_state = f_g*c_state + i_g*cc;
            float h_new = o_g * tanhf(c_state);
            int n = cta*8 + nl;
            g_h[b*HH + n] = h_new;
            g_ysT[((size_t)s*BB + b)*HH + n] = rna_tf32(h_new);
            if (s == SS-1) {
                const size_t OUT_H = (size_t)BB*SS*VV;
                out_hc[OUT_H + (size_t)b*HH + n] = h_new;
                out_hc[OUT_H + (size_t)BB*HH + (size_t)b*HH + n] = c_state;
            }
        }
        grid_barrier();
    }
}

// ---------------- launch ----------------
extern "C" void kernel_launch(void* const* d_in, const int* in_sizes, int n_in,
                              void* d_out, int out_size)
{
    const int*   x   = (const int*)  d_in[0];
    const float* emb = (const float*)d_in[1];
    const float* Wi  = (const float*)d_in[2];
    const float* bi  = (const float*)d_in[3];
    const float* Wf  = (const float*)d_in[4];
    const float* bf  = (const float*)d_in[5];
    const float* Wo  = (const float*)d_in[6];
    const float* bo  = (const float*)d_in[7];
    const float* Wc  = (const float*)d_in[8];
    const float* bc  = (const float*)d_in[9];
    const float* fcb = (const float*)d_in[10];
    float* out = (float*)d_out;

    void *p_xe, *p_wxp, *p_ysT, *p_embR, *p_xpart, *p_bpack;
    cudaGetSymbolAddress(&p_xe,    g_xe);
    cudaGetSymbolAddress(&p_wxp,   g_WxP);
    cudaGetSymbolAddress(&p_ysT,   g_ysT);
    cudaGetSymbolAddress(&p_embR,  g_embR);
    cudaGetSymbolAddress(&p_xpart, g_xpart);
    cudaGetSymbolAddress(&p_bpack, g_bpack);

    cudaFuncSetAttribute(lstm_rec, cudaFuncAttributeMaxDynamicSharedMemorySize, SMEM_SCAN);
    cudaFuncSetAttribute(gemm_mma<0, G4>, cudaFuncAttributeMaxDynamicSharedMemorySize, SMEM_GEMM);
    cudaFuncSetAttribute(gemm_mma<1, VV>, cudaFuncAttributeMaxDynamicSharedMemorySize, SMEM_GEMM);

    // 1) prep: pack weights (Wx tf32-rounded), round emb, gather+round token embeddings
    pack_kernel<<<G4, 256>>>(Wi, Wf, Wo, Wc, bi, bf, bo, bc);
    round_emb_kernel<<<(VV*HH/4)/256, 256>>>(emb);
    gather_xe_kernel<<<MM, 256>>>(x, emb);

    // 2) x-part GEMM on tensor cores: g_xpart = xe @ WxP.T + bpack
    gemm_mma<0, G4><<<dim3(MM/128, G4/128), 256, SMEM_GEMM>>>(
        (const float*)p_xe, (const float*)p_wxp, (const float*)p_bpack, (float*)p_xpart);

    // 3) recurrent scan (persistent, grid-synced)
    lstm_rec<<<GRID_R, THR_R, SMEM_SCAN>>>(out);

    // 4) tied output projection on tensor cores: logits = ysT @ embR.T + fcb
    gemm_mma<1, VV><<<dim3(MM/128, VV/128), 256, SMEM_GEMM>>>(
        (const float*)p_ysT, (const float*)p_embR, fcb, out);
}

// round 11
// speedup vs baseline: 1.0023x; 1.0023x over previous
#include <cuda_runtime.h>
#include <cstdint>
#include <math.h>

// Problem constants
#define BB 16
#define SS 256
#define VV 32000
#define HH 1024
#define MM (SS*BB)        // 4096 rows, time-major m = s*16+b
#define G4 (4*HH)         // 4096 packed gate columns

// ---------------- static device scratch ----------------
__device__ float g_WhP[G4*HH];            // recurrent weights fp32 [p][k]
__device__ float g_WxP[G4*HH];            // input weights, tf32-rounded [p][k]
__device__ float g_bpack[G4];
__device__ float g_xe  [(size_t)MM*HH];   // gathered embeddings, tf32-rounded
__device__ float g_embR[(size_t)VV*HH];   // emb tf32-rounded (projection B)
__device__ float g_xpart[(size_t)MM*G4];  // x@Wx.T + b
__device__ float g_ysT [(size_t)MM*HH];   // h history, tf32-rounded (projection A)
__device__ float g_h[BB*HH];
__device__ unsigned long long g_bar = 0ULL;

// ---------------- helpers ----------------
__device__ __forceinline__ uint32_t smem_u32(const void* p) {
    uint32_t a;
    asm("{ .reg .u64 t; cvta.to.shared.u64 t, %1; cvt.u32.u64 %0, t; }" : "=r"(a) : "l"(p));
    return a;
}
__device__ __forceinline__ float rna_tf32(float x) {
    uint32_t r;
    asm("cvt.rna.tf32.f32 %0, %1;" : "=r"(r) : "f"(x));
    return __uint_as_float(r);
}
__device__ __forceinline__ void cp_async16(uint32_t saddr, const void* gaddr) {
    asm volatile("cp.async.cg.shared.global [%0], [%1], 16;" :: "r"(saddr), "l"(gaddr));
}
__device__ __forceinline__ void cp_commit() {
    asm volatile("cp.async.commit_group;");
}
__device__ __forceinline__ void cp_wait1() {
    asm volatile("cp.async.wait_group 1;");
}
__device__ __forceinline__ void ldm_x4(uint32_t* r, uint32_t addr) {
    asm volatile("ldmatrix.sync.aligned.m8n8.x4.shared.b16 {%0,%1,%2,%3}, [%4];"
                 : "=r"(r[0]), "=r"(r[1]), "=r"(r[2]), "=r"(r[3]) : "r"(addr));
}
__device__ __forceinline__ void mma_tf32(float* c, const uint32_t* a, uint32_t b0, uint32_t b1) {
    asm volatile(
        "mma.sync.aligned.m16n8k8.row.col.f32.tf32.tf32.f32 "
        "{%0,%1,%2,%3}, {%4,%5,%6,%7}, {%8,%9}, {%0,%1,%2,%3};"
        : "+f"(c[0]), "+f"(c[1]), "+f"(c[2]), "+f"(c[3])
        : "r"(a[0]), "r"(a[1]), "r"(a[2]), "r"(a[3]), "r"(b0), "r"(b1));
}

// ---------------- prep kernels ----------------
__global__ void pack_kernel(const float* __restrict__ Wi, const float* __restrict__ Wf,
                            const float* __restrict__ Wo, const float* __restrict__ Wc,
                            const float* __restrict__ bi, const float* __restrict__ bf,
                            const float* __restrict__ bo, const float* __restrict__ bc)
{
    int idx4 = blockIdx.x*256 + threadIdx.x;     // over G4*256
    int p = idx4 >> 8, kq = idx4 & 255;
    int n = p >> 2, gt = p & 3;
    const float* W = (gt==0)?Wi:(gt==1)?Wf:(gt==2)?Wo:Wc;
    float4 vh = *(const float4*)(W + (size_t)n*2048 + kq*4);
    float4 vx = *(const float4*)(W + (size_t)n*2048 + 1024 + kq*4);
    *(float4*)(g_WhP + (size_t)p*HH + kq*4) = vh;
    vx.x = rna_tf32(vx.x); vx.y = rna_tf32(vx.y); vx.z = rna_tf32(vx.z); vx.w = rna_tf32(vx.w);
    *(float4*)(g_WxP + (size_t)p*HH + kq*4) = vx;
    if (kq == 0) {
        const float* bp = (gt==0)?bi:(gt==1)?bf:(gt==2)?bo:bc;
        g_bpack[p] = bp[n];
    }
}

__global__ void round_emb_kernel(const float* __restrict__ emb)
{
    size_t i = ((size_t)blockIdx.x*256 + threadIdx.x) * 4;   // VV*HH/4 threads
    float4 v = *(const float4*)(emb + i);
    v.x = rna_tf32(v.x); v.y = rna_tf32(v.y); v.z = rna_tf32(v.z); v.w = rna_tf32(v.w);
    *(float4*)(g_embR + i) = v;
}

__global__ void gather_xe_kernel(const int* __restrict__ x, const float* __restrict__ emb)
{
    int idx4 = blockIdx.x*256 + threadIdx.x;     // over MM*256
    int m = idx4 >> 8, q = idx4 & 255;
    int tok = x[(m & 15)*SS + (m >> 4)];
    float4 v = *(const float4*)(emb + (size_t)tok*HH + q*4);
    v.x = rna_tf32(v.x); v.y = rna_tf32(v.y); v.z = rna_tf32(v.z); v.w = rna_tf32(v.w);
    *(float4*)(g_xe + (size_t)m*HH + q*4) = v;
}

// ---------------- tf32 mma.sync NT GEMM: C[m][n] = A[m][:] . B[n][:] + bias[n] ----------------
// A: [rowsA][HH] row-major, B: [rowsB][HH] row-major (both tf32-rounded)
// MODE 0: C = g_xpart (row m direct, stride NN)
// MODE 1: C = logits, row remap m -> (m&15)*SS + (m>>4), stride NN
// CTA tile 128x128, 8 warps (2m x 4n), warp tile 64x32, mma m16n8k8, BK=32, 3-stage cp.async.
#define KTILE 32
#define KI (HH/KTILE)              // 32
#define ASTR 36                    // smem row stride in floats (pad 4)
#define STG_FLOATS (128*ASTR*2)    // A + B per stage = 9216 floats
#define SMEM_GEMM (3*STG_FLOATS*4) // 110592 bytes

template<int MODE, int NN>
__global__ void __launch_bounds__(256, 1)
gemm_mma(const float* __restrict__ A, const float* __restrict__ B,
         const float* __restrict__ bias, float* __restrict__ C)
{
    extern __shared__ __align__(128) float sm[];
    const int tid = threadIdx.x;
    const int wid = tid >> 5, lane = tid & 31;
    const int warp_m = wid >> 2;           // 0..1
    const int warp_n = wid & 3;            // 0..3
    const int m_base = blockIdx.x * 128;
    const int n_base = blockIdx.y * 128;

    // ---- loader precompute: 4 chunks of 16B for A and for B per thread ----
    int lrowA[4], lccA[4];
    #pragma unroll
    for (int i = 0; i < 4; i++) {
        int chunk = tid + i*256;           // 0..1023
        lrowA[i] = chunk >> 3;
        lccA[i]  = chunk & 7;
    }
    const uint32_t smb = smem_u32(sm);

    // ---- ldmatrix per-lane address pieces (A fragments) ----
    const int matid = lane >> 3;
    const int fr_row = (lane & 7) + (matid & 1)*8;
    const int fr_colb = (matid >> 1) * 16;          // byte offset within 32B k-step
    // byte addr of A fragment base (stage 0, mt=0, ko=0):
    const uint32_t a_frag_base = smb + (uint32_t)(warp_m*64 + fr_row) * (ASTR*4) + fr_colb;

    // ---- B fragment smem float-index base ----
    const int b_frag_base = 128*ASTR + (warp_n*32 + (lane >> 2))*ASTR + (lane & 3);

    float acc[4][4][4];
    #pragma unroll
    for (int mt = 0; mt < 4; mt++)
        #pragma unroll
        for (int nt = 0; nt < 4; nt++)
            #pragma unroll
            for (int r = 0; r < 4; r++) acc[mt][nt][r] = 0.f;

    // ---- async load of one k-tile into stage st ----
    auto issue = [&](int st, int kt) {
        float* As = sm + st*STG_FLOATS;
        float* Bs = As + 128*ASTR;
        #pragma unroll
        for (int i = 0; i < 4; i++) {
            const float* ga = A + (size_t)(m_base + lrowA[i])*HH + kt*KTILE + lccA[i]*4;
            const float* gb = B + (size_t)(n_base + lrowA[i])*HH + kt*KTILE + lccA[i]*4;
            cp_async16(smem_u32(&As[lrowA[i]*ASTR + lccA[i]*4]), ga);
            cp_async16(smem_u32(&Bs[lrowA[i]*ASTR + lccA[i]*4]), gb);
        }
        cp_commit();
    };

    issue(0, 0);
    issue(1, 1);

    for (int kt = 0; kt < KI; kt++) {
        cp_wait1();
        __syncthreads();
        if (kt + 2 < KI) issue((kt+2) % 3, kt+2);

        const int st = kt % 3;
        const uint32_t a_st = a_frag_base + (uint32_t)st * (STG_FLOATS*4);
        const float* Bs = sm + st*STG_FLOATS;

        #pragma unroll
        for (int ko = 0; ko < 4; ko++) {
            uint32_t afr[4][4];
            #pragma unroll
            for (int mt = 0; mt < 4; mt++)
                ldm_x4(afr[mt], a_st + mt*(16*ASTR*4) + ko*32);
            uint32_t b0[4], b1[4];
            #pragma unroll
            for (int nt = 0; nt < 4; nt++) {
                int bi_ = b_frag_base + nt*(8*ASTR) + ko*8;
                b0[nt] = __float_as_uint(Bs[bi_]);
                b1[nt] = __float_as_uint(Bs[bi_ + 4]);
            }
            #pragma unroll
            for (int mt = 0; mt < 4; mt++)
                #pragma unroll
                for (int nt = 0; nt < 4; nt++)
                    mma_tf32(acc[mt][nt], afr[mt], b0[nt], b1[nt]);
        }
    }

    // ---- epilogue: bias add + store ----
    #pragma unroll
    for (int mt = 0; mt < 4; mt++) {
        int r0 = m_base + warp_m*64 + mt*16 + (lane >> 2);
        int r1 = r0 + 8;
        size_t off0, off1;
        if (MODE == 0) {
            off0 = (size_t)r0 * NN;
            off1 = (size_t)r1 * NN;
        } else {
            off0 = (size_t)((r0 & 15)*SS + (r0 >> 4)) * (size_t)NN;
            off1 = (size_t)((r1 & 15)*SS + (r1 >> 4)) * (size_t)NN;
        }
        #pragma unroll
        for (int nt = 0; nt < 4; nt++) {
            int col = n_base + warp_n*32 + nt*8 + 2*(lane & 3);
            float2 bv = *(const float2*)(bias + col);
            float2 o0, o1;
            o0.x = acc[mt][nt][0] + bv.x; o0.y = acc[mt][nt][1] + bv.y;
            o1.x = acc[mt][nt][2] + bv.x; o1.y = acc[mt][nt][3] + bv.y;
            *(float2*)(C + off0 + col) = o0;
            *(float2*)(C + off1 + col) = o1;
        }
    }
}

// ---------------- persistent recurrent kernel ----------------
#define GRID_R 128
#define THR_R  256
#define WSH_STRIDE 36
#define HS_STRIDE  20
#define RED_STRIDE 36
#define SMEM_SCAN ((HH*WSH_STRIDE + HH*HS_STRIDE)*4)

__device__ __forceinline__ void grid_barrier() {
    __syncthreads();
    if (threadIdx.x == 0) {
        __threadfence();
        unsigned long long ticket = atomicAdd(&g_bar, 1ULL);
        unsigned long long target = (ticket / GRID_R + 1ULL) * (unsigned long long)GRID_R;
        while (*((volatile unsigned long long*)&g_bar) < target) { }
        __threadfence();
    }
    __syncthreads();
}

__global__ void __launch_bounds__(THR_R, 1) lstm_rec(float* __restrict__ out_hc)
{
    extern __shared__ float smr[];
    float* Wsh = smr;                        // [k][c], stride 36
    float* hs  = smr + HH*WSH_STRIDE;        // [k][b], stride 20 (reused as red buffer)

    const int tid = threadIdx.x;
    const int cta = blockIdx.x;
    const int tk = tid & 31;
    const int tb = (tid >> 5) & 1;
    const int tc = tid >> 6;
    const int b0 = tb*8, c0 = tc*8;

    {
        int c = tid >> 3, kq = tid & 7;
        const float* src = g_WhP + (size_t)(cta*32 + c)*HH;
        #pragma unroll 4
        for (int it = 0; it < 32; it++) {
            int k0 = kq*4 + it*32;
            float4 v = *(const float4*)(src + k0);
            Wsh[(k0+0)*WSH_STRIDE + c] = v.x;
            Wsh[(k0+1)*WSH_STRIDE + c] = v.y;
            Wsh[(k0+2)*WSH_STRIDE + c] = v.z;
            Wsh[(k0+3)*WSH_STRIDE + c] = v.w;
        }
    }
    if (tid < 128) g_h[cta*128 + tid] = 0.f;

    float c_state = 0.f;

    grid_barrier();

    for (int s = 0; s < SS; s++) {
        {
            int b = tid >> 4, nq = tid & 15;
            const float* hp = g_h + b*HH;
            #pragma unroll 4
            for (int it = 0; it < 16; it++) {
                int n0 = nq*4 + it*64;
                float4 v = __ldcg((const float4*)(hp + n0));
                hs[(n0+0)*HS_STRIDE + b] = v.x;
                hs[(n0+1)*HS_STRIDE + b] = v.y;
                hs[(n0+2)*HS_STRIDE + b] = v.z;
                hs[(n0+3)*HS_STRIDE + b] = v.w;
            }
        }
        __syncthreads();

        float acc[8][8];
        #pragma unroll
        for (int i = 0; i < 8; i++)
            #pragma unroll
            for (int j = 0; j < 8; j++) acc[i][j] = 0.f;

        #pragma unroll 4
        for (int kk = 0; kk < 32; kk++) {
            int k = kk*32 + tk;
            float a[8], w[8];
            *(float4*)&a[0] = *(const float4*)&hs[k*HS_STRIDE + b0];
            *(float4*)&a[4] = *(const float4*)&hs[k*HS_STRIDE + b0 + 4];
            *(float4*)&w[0] = *(const float4*)&Wsh[k*WSH_STRIDE + c0];
            *(float4*)&w[4] = *(const float4*)&Wsh[k*WSH_STRIDE + c0 + 4];
            #pragma unroll
            for (int i = 0; i < 8; i++)
                #pragma unroll
                for (int j = 0; j < 8; j++)
                    acc[i][j] += a[i]*w[j];
        }
        __syncthreads();

        float* red = hs;
        #pragma unroll
        for (int i = 0; i < 8; i++)
            #pragma unroll
            for (int j = 0; j < 8; j++)
                red[((c0+j)*16 + (b0+i))*RED_STRIDE + tk] = acc[i][j];
        __syncthreads();

        if (tid < 128) {
            int b = tid & 15, nl = tid >> 4;
            float g[4];
            #pragma unroll
            for (int gt = 0; gt < 4; gt++) {
                int cl = nl*4 + gt;
                const float* rp = red + (cl*16 + b)*RED_STRIDE;
                float ssum = 0.f;
                #pragma unroll
                for (int t = 0; t < 32; t += 4) {
                    float4 v = *(const float4*)(rp + t);
                    ssum += (v.x + v.y) + (v.z + v.w);
                }
                g[gt] = ssum + __ldcg(&g_xpart[((size_t)s*BB + b)*G4 + cta*32 + cl]);
            }
            float i_g = 1.f/(1.f + expf(-g[0]));
            float f_g = 1.f/(1.f + expf(-g[1]));
            float o_g = 1.f/(1.f + expf(-g[2]));
            float cc  = tanhf(g[3]);
            c_state = f_g*c_state + i_g*cc;
            float h_new = o_g * tanhf(c_state);
            int n = cta*8 + nl;
            g_h[b*HH + n] = h_new;
            g_ysT[((size_t)s*BB + b)*HH + n] = rna_tf32(h_new);
            if (s == SS-1) {
                const size_t OUT_H = (size_t)BB*SS*VV;
                out_hc[OUT_H + (size_t)b*HH + n] = h_new;
                out_hc[OUT_H + (size_t)BB*HH + (size_t)b*HH + n] = c_state;
            }
        }
        grid_barrier();
    }
}

// ---------------- launch ----------------
extern "C" void kernel_launch(void* const* d_in, const int* in_sizes, int n_in,
                              void* d_out, int out_size)
{
    const int*   x   = (const int*)  d_in[0];
    const float* emb = (const float*)d_in[1];
    const float* Wi  = (const float*)d_in[2];
    const float* bi  = (const float*)d_in[3];
    const float* Wf  = (const float*)d_in[4];
    const float* bf  = (const float*)d_in[5];
    const float* Wo  = (const float*)d_in[6];
    const float* bo  = (const float*)d_in[7];
    const float* Wc  = (const float*)d_in[8];
    const float* bc  = (const float*)d_in[9];
    const float* fcb = (const float*)d_in[10];
    float* out = (float*)d_out;

    void *p_xe, *p_wxp, *p_ysT, *p_embR, *p_xpart, *p_bpack;
    cudaGetSymbolAddress(&p_xe,    g_xe);
    cudaGetSymbolAddress(&p_wxp,   g_WxP);
    cudaGetSymbolAddress(&p_ysT,   g_ysT);
    cudaGetSymbolAddress(&p_embR,  g_embR);
    cudaGetSymbolAddress(&p_xpart, g_xpart);
    cudaGetSymbolAddress(&p_bpack, g_bpack);

    cudaFuncSetAttribute(lstm_rec, cudaFuncAttributeMaxDynamicSharedMemorySize, SMEM_SCAN);
    cudaFuncSetAttribute(gemm_mma<0, G4>, cudaFuncAttributeMaxDynamicSharedMemorySize, SMEM_GEMM);
    cudaFuncSetAttribute(gemm_mma<1, VV>, cudaFuncAttributeMaxDynamicSharedMemorySize, SMEM_GEMM);

    // 1) prep: pack weights (Wx tf32-rounded), round emb, gather+round token embeddings
    pack_kernel<<<G4, 256>>>(Wi, Wf, Wo, Wc, bi, bf, bo, bc);
    round_emb_kernel<<<(VV*HH/4)/256, 256>>>(emb);
    gather_xe_kernel<<<MM, 256>>>(x, emb);

    // 2) x-part GEMM on tensor cores: g_xpart = xe @ WxP.T + bpack
    gemm_mma<0, G4><<<dim3(MM/128, G4/128), 256, SMEM_GEMM>>>(
        (const float*)p_xe, (const float*)p_wxp, (const float*)p_bpack, (float*)p_xpart);

    // 3) recurrent scan (persistent, grid-synced)
    lstm_rec<<<GRID_R, THR_R, SMEM_SCAN>>>(out);

    // 4) tied output projection on tensor cores: logits = ysT @ embR.T + fcb
    gemm_mma<1, VV><<<dim3(MM/128, VV/128), 256, SMEM_GEMM>>>(
        (const float*)p_ysT, (const float*)p_embR, fcb, out);
}